// round 4
// baseline (speedup 1.0000x reference)
#include <cuda_runtime.h>
#include <cuda_fp16.h>
#include <math.h>

#define Bb 128
#define Rr 1152
#define CI 8
#define Cc 10
#define Oo 16
#define NCB (Cc*Bb)      /* 1280 */
#define NS  (NCB*Oo)     /* 20480 */
#define RT 32
#define NRT (Rr/RT)      /* 36 */
#define NIT 640          /* k_it CTA count (2 cb per CTA) */

// Static device scratch (no runtime allocation, no memset needed: every slot
// is fully written before it is read, every run).
__device__ __half g_uh[(size_t)Cc*Bb*Rr*Oo];  // 47 MB, u in fp16 (L2-resident)
__device__ float  g_part[NRT][NS];            // per-r-tile partial sums of u
__device__ float  g_S[NS];                    // current s[c][b][o]
__device__ float  g_V[NS];                    // accumulated V (pre-scaled log2e)
__device__ float  g_n2a[20];                  // sum-of-squares partials (after s1)
__device__ float  g_n2b[NIT];                 // after iter-2
__device__ float  g_n2c[NIT];                 // after iter-3

// ---------------------------------------------------------------------------
// fast 2^z: magic round + degree-4 poly, FMA/ALU pipes only. |err| ~4e-5.
// ---------------------------------------------------------------------------
__device__ __forceinline__ float fexp2f(float z) {
    const float MAGIC = 12582912.0f;           // 2^23 + 2^22
    float t  = z + MAGIC;
    float f  = z - (t - MAGIC);                // frac in [-0.5, 0.5]
    int   nb = __float_as_int(t) << 23;
    float p  = 0.0096181298f;
    p = fmaf(p, f, 0.0555041087f);
    p = fmaf(p, f, 0.2402265070f);
    p = fmaf(p, f, 0.6931471806f);
    p = fmaf(p, f, 1.0f);
    return __int_as_float(__float_as_int(p) + nb);
}

// ---------------------------------------------------------------------------
// k_u: u[c,b,r,o] = sum_i x[b,r,i]*W[c,r,i,o] -> fp16; per-(rt,c,b,o) partial
// sums of u -> g_part (for iter-1 uniform softmax: s1 = mean_r u).
// grid (NRT, C), 256 thr. W in regs, one barrier per b, no atomics.
// ---------------------------------------------------------------------------
__global__ __launch_bounds__(256) void k_u(const float* __restrict__ x,
                                           const float* __restrict__ W)
{
    const int rt  = blockIdx.x, c = blockIdx.y;
    const int tid = threadIdx.x;
    const int o2  = tid & 7;
    const int rl  = tid >> 3;          // 0..31
    const int r   = rt * RT + rl;
    const int w   = tid >> 5, lane = tid & 31;

    __shared__ float red0[2][8][8], red1[2][8][8];   // [buf][warp][o2]

    float w0[8], w1[8];
    {
        const float* Wp = W + (((size_t)c*Rr + r)*CI)*Oo + 2*o2;
        #pragma unroll
        for (int i = 0; i < 8; i++) {
            float2 v = *(const float2*)(Wp + i*Oo);
            w0[i] = v.x; w1[i] = v.y;
        }
    }

    const float4* xp = (const float4*)x;
    const size_t  xstep = (size_t)Rr*CI/4;
    const size_t  xbase = (size_t)r*CI/4;

    half2* udst = (half2*)g_uh + ((size_t)c*Bb*Rr + r)*8 + o2;

    float4 xa = xp[xbase], xb = xp[xbase+1];
    for (int b = 0; b < Bb; b++) {
        float4 na, nb;
        if (b + 1 < Bb) {
            size_t nx = xbase + (size_t)(b+1)*xstep;
            na = xp[nx]; nb = xp[nx+1];
        }
        float u0, u1;
        u0 =           xa.x*w0[0];        u1 =           xa.x*w1[0];
        u0 = fmaf(xa.y, w0[1], u0);       u1 = fmaf(xa.y, w1[1], u1);
        u0 = fmaf(xa.z, w0[2], u0);       u1 = fmaf(xa.z, w1[2], u1);
        u0 = fmaf(xa.w, w0[3], u0);       u1 = fmaf(xa.w, w1[3], u1);
        u0 = fmaf(xb.x, w0[4], u0);       u1 = fmaf(xb.x, w1[4], u1);
        u0 = fmaf(xb.y, w0[5], u0);       u1 = fmaf(xb.y, w1[5], u1);
        u0 = fmaf(xb.z, w0[6], u0);       u1 = fmaf(xb.z, w1[6], u1);
        u0 = fmaf(xb.w, w0[7], u0);       u1 = fmaf(xb.w, w1[7], u1);

        udst[(size_t)b*Rr*8] = __floats2half2_rn(u0, u1);

        // reduce the 4 r-rows held by this warp (lane bits 3,4)
        float p0 = u0, p1 = u1;
        p0 += __shfl_xor_sync(0xffffffffu, p0, 8);
        p1 += __shfl_xor_sync(0xffffffffu, p1, 8);
        p0 += __shfl_xor_sync(0xffffffffu, p0, 16);
        p1 += __shfl_xor_sync(0xffffffffu, p1, 16);
        const int buf = b & 1;
        if (lane < 8) { red0[buf][w][lane] = p0; red1[buf][w][lane] = p1; }
        __syncthreads();
        if (tid < 16) {
            float t = 0.f;
            int o;
            if (tid < 8) {
                #pragma unroll
                for (int j = 0; j < 8; j++) t += red0[buf][j][tid];
                o = 2*tid;
            } else {
                #pragma unroll
                for (int j = 0; j < 8; j++) t += red1[buf][j][tid-8];
                o = 2*(tid-8)+1;
            }
            g_part[rt][(c*Bb + b)*16 + o] = t;
        }
        xa = na; xb = nb;
    }
}

// ---------------------------------------------------------------------------
// k_s1: s1 = (sum_rt g_part)/R -> g_S; per-CTA sum of s1^2 -> g_n2a.
// grid 20 x 1024, fully coalesced.
// ---------------------------------------------------------------------------
__global__ __launch_bounds__(1024) void k_s1()
{
    const int tid = threadIdx.x;
    const int i   = blockIdx.x*1024 + tid;
    float s = 0.f;
    #pragma unroll
    for (int rt = 0; rt < NRT; rt++) s += g_part[rt][i];
    s *= (1.0f / (float)Rr);
    g_S[i] = s;

    __shared__ float sh[1024];
    sh[tid] = s*s;
    __syncthreads();
    for (int st = 512; st > 0; st >>= 1) {
        if (tid < st) sh[tid] += sh[tid + st];
        __syncthreads();
    }
    if (tid == 0) g_n2a[blockIdx.x] = sh[0];
}

// ---------------------------------------------------------------------------
// k_it: consumer computes f from n2 partials, forms V, streams u (L2-resident),
// softmax-weighted sums -> g_S; per-CTA sum s^2 -> n2out.
// iter3==0: V = f*L2E*s_prev, also stores it to g_V.
// iter3==1: V = g_V + f*L2E*s_prev.
// grid (B/2, C) = 640 CTAs, 256 thr, 2 cb per CTA.
// ---------------------------------------------------------------------------
__global__ __launch_bounds__(256) void k_it(const float* __restrict__ n2part,
                                            int n2n, float* __restrict__ n2out,
                                            int iter3)
{
    const int bx = blockIdx.x, c = blockIdx.y;
    const int tid = threadIdx.x;
    const int p = (tid & 1) * 8;
    __shared__ float zs[256*8];
    __shared__ float ss[256*8];
    __shared__ float shn[256];

    // global n2 -> squash factor f (same value in every CTA, deterministic)
    float acc = 0.f;
    for (int i = tid; i < n2n; i += 256) acc += n2part[i];
    shn[tid] = acc;
    __syncthreads();
    for (int st = 128; st > 0; st >>= 1) {
        if (tid < st) shn[tid] += shn[tid + st];
        __syncthreads();
    }
    const float n2 = shn[0];
    const float K  = (sqrtf(n2) / (1.0f + n2)) * 1.4426950408889634f;

    float qacc = 0.f;   // this thread's contribution to sum s_new^2 (tid<16)

    for (int bb = 0; bb < 2; bb++) {
        const int b  = bx*2 + bb;
        const int cb = c*Bb + b;

        float V[8];
        #pragma unroll
        for (int j = 0; j < 8; j++) {
            const int idx = cb*16 + p + j;
            float v = K * g_S[idx];
            if (iter3) v += g_V[idx];
            V[j] = v;
        }
        if (!iter3 && tid < 16) g_V[cb*16 + tid] = K * g_S[cb*16 + tid];

        const float4* up = (const float4*)(g_uh + (size_t)cb*Rr*Oo);
        float z[8], s[8];
        #pragma unroll
        for (int j = 0; j < 8; j++) { z[j] = 0.f; s[j] = 0.f; }

        #pragma unroll 3
        for (int k = 0; k < 9; k++) {
            float4 raw = up[tid + k*256];
            const half2* hp = (const half2*)&raw;
            #pragma unroll
            for (int j = 0; j < 4; j++) {
                float2 f2 = __half22float2(hp[j]);
                float e0 = fexp2f(f2.x * V[2*j]);
                float e1 = fexp2f(f2.y * V[2*j+1]);
                z[2*j]   += e0;  s[2*j]   = fmaf(e0, f2.x, s[2*j]);
                z[2*j+1] += e1;  s[2*j+1] = fmaf(e1, f2.y, s[2*j+1]);
            }
        }

        const int row = (tid >> 1) + (tid & 1)*128;
        #pragma unroll
        for (int j = 0; j < 8; j++) { zs[row*8+j] = z[j]; ss[row*8+j] = s[j]; }
        __syncthreads();
        if (tid < 16) {
            const int base = (tid & 8) ? 128*8 : 0;
            const int col  = tid & 7;
            float zt = 0.f, st = 0.f;
            #pragma unroll 8
            for (int t = 0; t < 128; t++) {
                zt += zs[base + t*8 + col];
                st += ss[base + t*8 + col];
            }
            const float sn = st / zt;
            g_S[cb*16 + tid] = sn;       // exclusive per-cb ownership
            qacc += sn * sn;
        }
        __syncthreads();
    }

    // per-CTA sum of s_new^2 (only tid<16 contributed)
    shn[tid] = (tid < 16) ? qacc : 0.f;
    __syncthreads();
    for (int st = 8; st > 0; st >>= 1) {
        if (tid < st) shn[tid] += shn[tid + st];
        __syncthreads();
    }
    if (tid == 0) n2out[blockIdx.y*gridDim.x + blockIdx.x] = shn[0];
}

// ---------------------------------------------------------------------------
// k_fin: out = f3 * s3. grid 20 x 1024.
// ---------------------------------------------------------------------------
__global__ __launch_bounds__(1024) void k_fin(float* __restrict__ outp)
{
    const int tid = threadIdx.x;
    __shared__ float sh[1024];
    sh[tid] = (tid < NIT) ? g_n2c[tid] : 0.f;
    __syncthreads();
    for (int st = 512; st > 0; st >>= 1) {
        if (tid < st) sh[tid] += sh[tid + st];
        __syncthreads();
    }
    const float n2 = sh[0];
    const float f  = sqrtf(n2) / (1.0f + n2);
    const int i = blockIdx.x*1024 + tid;
    outp[i] = f * g_S[i];
}

// ---------------------------------------------------------------------------
extern "C" void kernel_launch(void* const* d_in, const int* in_sizes, int n_in,
                              void* d_out, int out_size)
{
    const float* x = (const float*)d_in[0];   // [128,1152,8]
    const float* W = (const float*)d_in[1];   // [10,1152,8,16]
    float* out = (float*)d_out;               // 20480 floats
    (void)in_sizes; (void)n_in; (void)out_size;

    float *n2a, *n2b, *n2c;
    cudaGetSymbolAddress((void**)&n2a, g_n2a);
    cudaGetSymbolAddress((void**)&n2b, g_n2b);
    cudaGetSymbolAddress((void**)&n2c, g_n2c);

    k_u  <<<dim3(NRT, Cc), 256>>>(x, W);
    k_s1 <<<20, 1024>>>();                          // iter 1 (uniform) + n2
    k_it <<<dim3(Bb/2, Cc), 256>>>(n2a,  20, n2b, 0);  // iter 2
    k_it <<<dim3(Bb/2, Cc), 256>>>(n2b, NIT, n2c, 1);  // iter 3
    k_fin<<<20, 1024>>>(out);                        // final squash -> output
}

// round 5
// speedup vs baseline: 2.6592x; 2.6592x over previous
#include <cuda_runtime.h>
#include <cuda_fp16.h>
#include <math.h>

#define Bb 128
#define Rr 1152
#define CI 8
#define Cc 10
#define Oo 16
#define NS  (Cc*Bb*Oo)   /* 20480 */
#define RT 16
#define NRT (Rr/RT)      /* 72 */
#define NIT 640          /* # n2 partial slots */

// Static device scratch. Every slot written before read each run; no memset.
__device__ __half g_uh[(size_t)Cc*Bb*Rr*Oo];  // 47 MB, u in fp16
__device__ float  g_S[NS];                    // current s[c][b][o]
__device__ float  g_V[NS];                    // accumulated V (pre-scaled log2e)
__device__ float  g_n2a[NIT];                 // sum-sq partials after s1
__device__ float  g_n2b[NIT];                 // after iter-2
__device__ float  g_n2c[NIT];                 // after iter-3

// ---------------------------------------------------------------------------
// e = 2^(u*V): FFMA-fused magic-round + deg-4 poly. FMA/ALU pipes only.
// ---------------------------------------------------------------------------
__device__ __forceinline__ float fexp2_mul(float u, float V) {
    const float MAGIC = 12582912.0f;            // 2^23 + 2^22
    float t = fmaf(u, V, MAGIC);                // z+MAGIC, single rounding
    float g = t - MAGIC;                        // n (exact)
    float f = fmaf(u, V, -g);                   // frac = z - n, single rounding
    int  nb = __float_as_int(t) << 23;          // n * 2^23 (low 9 bits of MAGIC=0)
    float p = 0.0096181298f;
    p = fmaf(p, f, 0.0555041087f);
    p = fmaf(p, f, 0.2402265070f);
    p = fmaf(p, f, 0.6931471806f);
    p = fmaf(p, f, 1.0f);
    return __int_as_float(__float_as_int(p) + nb);
}

// ---------------------------------------------------------------------------
// k_u: u[c,b,r,o] = sum_i x[b,r,i]*W[c,r,i,o] -> fp16. Pure compute: no smem,
// no barriers, no reductions. grid (NRT, C) = 720 CTAs x 128 thr.
// Thread: one r (rt*16 + tid>>3), one o-pair (2*(tid&7)).
// ---------------------------------------------------------------------------
__global__ __launch_bounds__(128) void k_u(const float* __restrict__ x,
                                           const float* __restrict__ W)
{
    const int rt  = blockIdx.x, c = blockIdx.y;
    const int tid = threadIdx.x;
    const int o2  = tid & 7;
    const int rl  = tid >> 3;          // 0..15
    const int r   = rt * RT + rl;

    float w0[8], w1[8];
    {
        const float* Wp = W + (((size_t)c*Rr + r)*CI)*Oo + 2*o2;
        #pragma unroll
        for (int i = 0; i < 8; i++) {
            float2 v = *(const float2*)(Wp + i*Oo);
            w0[i] = v.x; w1[i] = v.y;
        }
    }

    const float4* xp = (const float4*)x;
    const size_t  xstep = (size_t)Rr*CI/4;
    const size_t  xbase = (size_t)r*CI/4;

    half2* udst = (half2*)g_uh + ((size_t)c*Bb*Rr + r)*8 + o2;

    float4 xa = xp[xbase], xb = xp[xbase+1];
    for (int b = 0; b < Bb; b++) {
        float4 na, nb;
        if (b + 1 < Bb) {
            size_t nx = xbase + (size_t)(b+1)*xstep;
            na = xp[nx]; nb = xp[nx+1];
        }
        float u0, u1;
        u0 =           xa.x*w0[0];        u1 =           xa.x*w1[0];
        u0 = fmaf(xa.y, w0[1], u0);       u1 = fmaf(xa.y, w1[1], u1);
        u0 = fmaf(xa.z, w0[2], u0);       u1 = fmaf(xa.z, w1[2], u1);
        u0 = fmaf(xa.w, w0[3], u0);       u1 = fmaf(xa.w, w1[3], u1);
        u0 = fmaf(xb.x, w0[4], u0);       u1 = fmaf(xb.x, w1[4], u1);
        u0 = fmaf(xb.y, w0[5], u0);       u1 = fmaf(xb.y, w1[5], u1);
        u0 = fmaf(xb.z, w0[6], u0);       u1 = fmaf(xb.z, w1[6], u1);
        u0 = fmaf(xb.w, w0[7], u0);       u1 = fmaf(xb.w, w1[7], u1);
        udst[(size_t)b*Rr*8] = __floats2half2_rn(u0, u1);
        xa = na; xb = nb;
    }
}

// ---------------------------------------------------------------------------
// k_s0: s1[cb,o] = mean_r u; per-CTA sum s1^2 -> g_n2a. grid (64,10), 256 thr,
// 2 cb per CTA. u streamed with full-unroll MLP (memory-bound kernel).
// ---------------------------------------------------------------------------
__global__ __launch_bounds__(256) void k_s0()
{
    const int bx = blockIdx.x, c = blockIdx.y;
    const int tid = threadIdx.x;
    __shared__ float ss[8*256];     // column-major: ss[j*256 + row]
    __shared__ float pA[256];
    __shared__ float shn[256];

    float qacc = 0.f;
    for (int bb = 0; bb < 2; bb++) {
        const int cb = c*Bb + bx*2 + bb;
        const float4* up = (const float4*)(g_uh + (size_t)cb*Rr*Oo);

        float s[8];
        #pragma unroll
        for (int j = 0; j < 8; j++) s[j] = 0.f;
        #pragma unroll
        for (int k = 0; k < 9; k++) {
            float4 raw = up[tid + k*256];
            const half2* hp = (const half2*)&raw;
            #pragma unroll
            for (int j = 0; j < 4; j++) {
                float2 f2 = __half22float2(hp[j]);
                s[2*j]   += f2.x;
                s[2*j+1] += f2.y;
            }
        }
        const int row = (tid >> 1) + (tid & 1)*128;
        #pragma unroll
        for (int j = 0; j < 8; j++) ss[j*256 + row] = s[j];
        __syncthreads();
        // stage A: thread (h,col,grp) sums rows h*128 + grp + 16*i
        {
            const int h = tid >> 7, col = (tid >> 4) & 7, grp = tid & 15;
            float a = 0.f;
            #pragma unroll
            for (int i = 0; i < 8; i++) a += ss[col*256 + h*128 + grp + 16*i];
            pA[tid] = a;
        }
        __syncthreads();
        if (tid < 16) {
            const int h = tid >> 3, col = tid & 7;
            float st = 0.f;
            #pragma unroll
            for (int g2 = 0; g2 < 16; g2++) st += pA[h*128 + col*16 + g2];
            const float sn = st * (1.0f / (float)Rr);
            g_S[cb*16 + tid] = sn;
            qacc += sn * sn;
        }
        __syncthreads();
    }
    shn[tid] = qacc;
    __syncthreads();
    if (tid == 0) {
        float t = 0.f;
        #pragma unroll
        for (int i = 0; i < 16; i++) t += shn[i];
        g_n2a[blockIdx.y*gridDim.x + blockIdx.x] = t;
    }
}

// ---------------------------------------------------------------------------
// k_it: compute f from n2 partials -> V; stream u with exp -> s_new, n2out.
// iter3==0: V = K*s_prev (stored to g_V).  iter3==1: V = g_V + K*s_prev.
// grid (64,10), 256 thr, 2 cb per CTA, 3-deep load pipeline.
// ---------------------------------------------------------------------------
__global__ __launch_bounds__(256) void k_it(const float* __restrict__ n2part,
                                            float* __restrict__ n2out,
                                            int iter3)
{
    const int bx = blockIdx.x, c = blockIdx.y;
    const int tid = threadIdx.x;
    const int p = (tid & 1) * 8;
    __shared__ float zs[8*256], ssm[8*256];     // column-major
    __shared__ float pAz[256], pAs[256];
    __shared__ float shn[256];

    // global n2 -> K (same in every CTA)
    float acc = n2part[tid] + n2part[tid + 256];
    if (tid < NIT - 512) acc += n2part[tid + 512];
    shn[tid] = acc;
    __syncthreads();
    for (int st = 128; st > 0; st >>= 1) {
        if (tid < st) shn[tid] += shn[tid + st];
        __syncthreads();
    }
    const float n2 = shn[0];
    const float K  = (sqrtf(n2) / (1.0f + n2)) * 1.4426950408889634f;

    float qacc = 0.f;
    for (int bb = 0; bb < 2; bb++) {
        const int cb = c*Bb + bx*2 + bb;

        float V[8];
        #pragma unroll
        for (int j = 0; j < 8; j++) {
            const int idx = cb*16 + p + j;
            float v = K * g_S[idx];
            if (iter3) v += g_V[idx];
            V[j] = v;
        }
        if (!iter3 && tid < 16) g_V[cb*16 + tid] = K * g_S[cb*16 + tid];

        const float4* up = (const float4*)(g_uh + (size_t)cb*Rr*Oo);
        float z[8], s[8];
        #pragma unroll
        for (int j = 0; j < 8; j++) { z[j] = 0.f; s[j] = 0.f; }

        float4 q0 = up[tid], q1 = up[tid + 256], q2 = up[tid + 512];
        #pragma unroll
        for (int k = 0; k < 9; k++) {
            float4 cur = q0; q0 = q1; q1 = q2;
            if (k < 6) q2 = up[tid + (k+3)*256];
            const half2* hp = (const half2*)&cur;
            #pragma unroll
            for (int j = 0; j < 4; j++) {
                float2 f2 = __half22float2(hp[j]);
                float e0 = fexp2_mul(f2.x, V[2*j]);
                float e1 = fexp2_mul(f2.y, V[2*j+1]);
                z[2*j]   += e0;  s[2*j]   = fmaf(e0, f2.x, s[2*j]);
                z[2*j+1] += e1;  s[2*j+1] = fmaf(e1, f2.y, s[2*j+1]);
            }
        }

        const int row = (tid >> 1) + (tid & 1)*128;
        #pragma unroll
        for (int j = 0; j < 8; j++) { zs[j*256 + row] = z[j]; ssm[j*256 + row] = s[j]; }
        __syncthreads();
        {
            const int h = tid >> 7, col = (tid >> 4) & 7, grp = tid & 15;
            float az = 0.f, as = 0.f;
            #pragma unroll
            for (int i = 0; i < 8; i++) {
                const int a = col*256 + h*128 + grp + 16*i;
                az += zs[a]; as += ssm[a];
            }
            pAz[tid] = az; pAs[tid] = as;
        }
        __syncthreads();
        if (tid < 16) {
            const int h = tid >> 3, col = tid & 7;
            float zt = 0.f, st = 0.f;
            #pragma unroll
            for (int g2 = 0; g2 < 16; g2++) {
                const int a = h*128 + col*16 + g2;
                zt += pAz[a]; st += pAs[a];
            }
            const float sn = st / zt;
            g_S[cb*16 + tid] = sn;
            qacc += sn * sn;
        }
        __syncthreads();
    }

    shn[tid] = qacc;
    __syncthreads();
    if (tid == 0) {
        float t = 0.f;
        #pragma unroll
        for (int i = 0; i < 16; i++) t += shn[i];
        n2out[blockIdx.y*gridDim.x + blockIdx.x] = t;
    }
}

// ---------------------------------------------------------------------------
// k_fin: out = f3 * s3. grid 20 x 1024.
// ---------------------------------------------------------------------------
__global__ __launch_bounds__(1024) void k_fin(float* __restrict__ outp)
{
    const int tid = threadIdx.x;
    __shared__ float sh[1024];
    sh[tid] = (tid < NIT) ? g_n2c[tid] : 0.f;
    __syncthreads();
    for (int st = 512; st > 0; st >>= 1) {
        if (tid < st) sh[tid] += sh[tid + st];
        __syncthreads();
    }
    const float n2 = sh[0];
    const float f  = sqrtf(n2) / (1.0f + n2);
    const int i = blockIdx.x*1024 + tid;
    outp[i] = f * g_S[i];
}

// ---------------------------------------------------------------------------
extern "C" void kernel_launch(void* const* d_in, const int* in_sizes, int n_in,
                              void* d_out, int out_size)
{
    const float* x = (const float*)d_in[0];   // [128,1152,8]
    const float* W = (const float*)d_in[1];   // [10,1152,8,16]
    float* out = (float*)d_out;               // 20480 floats
    (void)in_sizes; (void)n_in; (void)out_size;

    float *n2a, *n2b, *n2c;
    cudaGetSymbolAddress((void**)&n2a, g_n2a);
    cudaGetSymbolAddress((void**)&n2b, g_n2b);
    cudaGetSymbolAddress((void**)&n2c, g_n2c);

    k_u  <<<dim3(NRT, Cc), 128>>>(x, W);
    k_s0 <<<dim3(Bb/2, Cc), 256>>>();             // iter 1 (uniform) + n2
    k_it <<<dim3(Bb/2, Cc), 256>>>(n2a, n2b, 0);  // iter 2
    k_it <<<dim3(Bb/2, Cc), 256>>>(n2b, n2c, 1);  // iter 3
    k_fin<<<20, 1024>>>(out);                     // final squash -> output
}